// round 11
// baseline (speedup 1.0000x reference)
#include <cuda_runtime.h>
#include <cuda_fp16.h>
#include <cstdint>

// ---------------------------------------------------------------------------
// ChannelProjection via mma.sync (HMMA fp16, base-target ISA).
// R10: heterogeneous grid — every 3rd block is a pure-streaming block doing
// the z2/odd-channel path; the rest are GEMM blocks (R9 pipeline minus the
// z2 phase). Streaming CTAs keep DRAM busy while GEMM CTAs compute.
// ---------------------------------------------------------------------------

#define C_TOT   128
#define CC      64
#define HW      36864
#define NSAMP   16
#define CHW     (C_TOT * HW)
#define NPIX    (NSAMP * HW)
#define RED_BLOCKS  64
#define RED_THREADS 256

#define TPB       8
#define BLOCKS_PER_SAMPLE 72            // 72 * 8 * 64 = 36864 px
#define GEMM_BLOCKS (NSAMP * BLOCKS_PER_SAMPLE)   // 1152
#define STREAM_BLOCKS 576               // z2 path: 16 samp x 36 blocks
#define TOTAL_GRID (GEMM_BLOCKS + STREAM_BLOCKS)  // 1728
#define HW4 (HW / 4)                    // 9216 float4 per channel row

// smem offsets; strides: A/W1 rows 144B (72 fp16), S/W2 rows 272B (136 fp16)
#define OFF_W1    0          // [128h][72k]   18432
#define OFF_W2    18432      // [64o][136h]   17408
#define OFF_AHI   35840      // [64px][72k]    9216  (Y fp32 [64o][68] aliases A)
#define OFF_ALO   45056      //                9216
#define OFF_S     54272      // [64px][136h]  17408
#define OFF_Z0    71680      // raw z1 fp32 [64c][64px], buffer 0: 16384
#define OFF_Z1    88064      // buffer 1: 16384
#define OFF_B1    104448     // 128 f32
#define OFF_B2    104960     // 64 f32
#define SMEM_MAIN 105216

__device__ float g_psum[NSAMP * RED_BLOCKS];
__device__ float g_psq [NSAMP * RED_BLOCKS];
__device__ float g_mu  [NSAMP];
__device__ float g_rs  [NSAMP];
__device__ uint4 g_w1h[1152];   // 128*72 fp16
__device__ uint4 g_w2h[1088];   // 64*136 fp16

// ---------------- helpers ---------------------------------------------------
__device__ __forceinline__ uint32_t smem_u32(const void* p) {
    uint32_t a;
    asm("{ .reg .u64 t; cvta.to.shared.u64 t, %1; cvt.u32.u64 %0, t; }"
        : "=r"(a) : "l"(p));
    return a;
}
__device__ __forceinline__ void ldsm_x4(uint32_t (&r)[4], uint32_t addr) {
    asm volatile("ldmatrix.sync.aligned.m8n8.x4.shared.b16 {%0,%1,%2,%3}, [%4];"
                 : "=r"(r[0]), "=r"(r[1]), "=r"(r[2]), "=r"(r[3]) : "r"(addr));
}
__device__ __forceinline__ void ldsm_x2(uint32_t& r0, uint32_t& r1, uint32_t addr) {
    asm volatile("ldmatrix.sync.aligned.m8n8.x2.shared.b16 {%0,%1}, [%2];"
                 : "=r"(r0), "=r"(r1) : "r"(addr));
}
__device__ __forceinline__ void mma_f16(float (&c)[4], const uint32_t (&a)[4],
                                        uint32_t b0, uint32_t b1) {
    asm volatile(
        "mma.sync.aligned.m16n8k16.row.col.f32.f16.f16.f32 "
        "{%0,%1,%2,%3}, {%4,%5,%6,%7}, {%8,%9}, {%0,%1,%2,%3};"
        : "+f"(c[0]), "+f"(c[1]), "+f"(c[2]), "+f"(c[3])
        : "r"(a[0]), "r"(a[1]), "r"(a[2]), "r"(a[3]), "r"(b0), "r"(b1));
}
__device__ __forceinline__ uint32_t packh(__half a, __half b) {
    __half2 h; h.x = a; h.y = b;
    return *(uint32_t*)&h;
}
__device__ __forceinline__ void split2h(float v0, float v1, uint32_t& hi, uint32_t& lo) {
    const __half h0 = __float2half_rn(v0);
    const __half h1 = __float2half_rn(v1);
    const __half l0 = __float2half_rn(v0 - __half2float(h0));
    const __half l1 = __float2half_rn(v1 - __half2float(h1));
    hi = packh(h0, h1);
    lo = packh(l0, l1);
}
__device__ __forceinline__ float silu_f(float h) {
    return __fdividef(h, 1.f + __expf(-h));
}
__device__ __forceinline__ void cpasync16(uint32_t dst, const void* src) {
    asm volatile("cp.async.cg.shared.global [%0], [%1], 16;" :: "r"(dst), "l"(src));
}
#define CP_COMMIT() asm volatile("cp.async.commit_group;" ::: "memory")
#define CP_WAIT0()  asm volatile("cp.async.wait_group 0;" ::: "memory")

// ---------------- stage 1: per-sample partial sums --------------------------
__global__ void cp_stats_kernel(const float* __restrict__ z0) {
    const int b = blockIdx.y;
    const float4* z4 = (const float4*)(z0 + (size_t)b * CHW);
    const int n4 = CHW / 4;
    float s = 0.f, q = 0.f;
    for (int i = blockIdx.x * RED_THREADS + threadIdx.x; i < n4;
         i += RED_BLOCKS * RED_THREADS) {
        float4 v = z4[i];
        s += (v.x + v.y) + (v.z + v.w);
        q += (v.x * v.x + v.y * v.y) + (v.z * v.z + v.w * v.w);
    }
    #pragma unroll
    for (int off = 16; off; off >>= 1) {
        s += __shfl_down_sync(0xffffffffu, s, off);
        q += __shfl_down_sync(0xffffffffu, q, off);
    }
    __shared__ float ss[RED_THREADS / 32], sq[RED_THREADS / 32];
    const int w = threadIdx.x >> 5;
    if ((threadIdx.x & 31) == 0) { ss[w] = s; sq[w] = q; }
    __syncthreads();
    if (threadIdx.x == 0) {
        float S = 0.f, Q = 0.f;
        #pragma unroll
        for (int i = 0; i < RED_THREADS / 32; i++) { S += ss[i]; Q += sq[i]; }
        g_psum[b * RED_BLOCKS + blockIdx.x] = S;
        g_psq [b * RED_BLOCKS + blockIdx.x] = Q;
    }
}

// ---------------- stage 2: finalize + fp16 weights --------------------------
__global__ void cp_finalize_kernel(const float* __restrict__ w1,
                                   const float* __restrict__ w2) {
    const int t = threadIdx.x;   // 256
    if (t < NSAMP) {
        float S = 0.f, Q = 0.f;
        for (int i = 0; i < RED_BLOCKS; i++) {
            S += g_psum[t * RED_BLOCKS + i];
            Q += g_psq [t * RED_BLOCKS + i];
        }
        const float inv_n = 1.f / (float)CHW;
        const float mu  = S * inv_n;
        const float var = Q * inv_n - mu * mu;
        g_mu[t] = mu;
        g_rs[t] = rsqrtf(var + 1e-5f);
    }
    __half* w1h = (__half*)g_w1h;
    __half* w2h = (__half*)g_w2h;
    for (int i = t; i < 128 * 64; i += 256) {      // w1[h][k] -> [h][72]
        const int h = i >> 6, k = i & 63;
        w1h[h * 72 + k] = __float2half_rn(w1[h * 64 + k]);
    }
    for (int i = t; i < 64 * 128; i += 256) {      // w2[o][h] -> [o][136]
        const int o = i >> 7, h = i & 127;
        w2h[o * 136 + h] = __float2half_rn(w2[o * 128 + h]);
    }
}

// ---------------- stage 3: heterogeneous main kernel ------------------------
__global__ void __launch_bounds__(256, 2)
cp_main_kernel(const float* __restrict__ z0,
               const float* __restrict__ b1,
               const float* __restrict__ b2,
               float* __restrict__ out) {
    extern __shared__ char smc[];
    const int tid = threadIdx.x;
    const int bx = blockIdx.x;

    // ======================= streaming blocks (z2 path) =====================
    if ((bx % 3) == 2) {
        const int s    = bx / 3;              // 0..575
        const int samp = s / 36;
        const int blk  = s % 36;
        const float mu = g_mu[samp];
        const float rs = g_rs[samp];
        const float* zbs = z0 + (size_t)samp * CHW;
        float*       obs = out + (size_t)samp * CHW;
        const float4* z2v = (const float4*)(zbs + (size_t)CC * HW);
        const int base = blk * 16384;         // float4 units; 36*16384 = 64*HW4
        #pragma unroll 4
        for (int j = tid; j < 16384; j += 256) {
            const int local = base + j;
            const int c = local / HW4;
            const int p = local - c * HW4;
            const float4 zv = z2v[local];
            const float4 rv = ((const float4*)(zbs + (size_t)(2 * c + 1) * HW))[p];
            float4 ov;
            ov.x = (zv.x - mu) * rs + rv.x; ov.y = (zv.y - mu) * rs + rv.y;
            ov.z = (zv.z - mu) * rs + rv.z; ov.w = (zv.w - mu) * rs + rv.w;
            ((float4*)(obs + (size_t)(2 * c + 1) * HW))[p] = ov;
        }
        return;
    }

    // ========================== GEMM blocks =================================
    const int gb = (bx / 3) * 2 + (bx % 3);   // 0..1151
    const uint32_t sb = smem_u32(smc);
    const int w = tid >> 5, lane = tid & 31;
    const int g = lane >> 2, tig = lane & 3;
    const int lrow = lane & 15, lk = lane >> 4;          // ldsm.x4 mapping
    const int brow = lane & 7,  bk = (lane >> 3) & 1;    // ldsm.x2 mapping
    const int pg = w & 3;          // pixel group (16 px)
    const int hh = w >> 2;         // h-half (GEMM1) / o-half (GEMM2)

    const int b = gb / BLOCKS_PER_SAMPLE;
    const float* zb = z0 + (size_t)b * CHW;
    float*       ob = out + (size_t)b * CHW;
    const int p_base = (gb % BLOCKS_PER_SAMPLE) * (TPB * 64);

    // ---- prologue: issue cp.async for tile 0 (overlaps weight staging) ----
    for (int i = tid; i < 1024; i += 256) {        // 64ch x 16 float4
        const int c = i >> 4, f = (i & 15) * 4;
        cpasync16(sb + OFF_Z0 + (c * 64 + f) * 4, zb + (size_t)c * HW + p_base + f);
    }
    CP_COMMIT();

    // ---- stage weights + biases ----
    for (int i = tid; i < 1152; i += 256) ((uint4*)(smc + OFF_W1))[i] = g_w1h[i];
    for (int i = tid; i < 1088; i += 256) ((uint4*)(smc + OFF_W2))[i] = g_w2h[i];
    float* b1s = (float*)(smc + OFF_B1);
    float* b2s = (float*)(smc + OFF_B2);
    if (tid < 128) b1s[tid] = b1[tid];
    if (tid < 64)  b2s[tid] = b2[tid];

    const float mu = g_mu[b];
    const float rs = g_rs[b];
    float* Y = (float*)(smc + OFF_AHI);    // fp32 [o=64][stride 68] aliases A

    for (int tl = 0; tl < TPB; tl++) {
        const int p0 = p_base + tl * 64;
        const uint32_t bufc = (tl & 1) ? OFF_Z1 : OFF_Z0;
        const float* raw = (const float*)(smc + bufc);

        CP_WAIT0();
        __syncthreads();   // raw[tl] landed; S/Y free from prev tile

        // ---- convert: raw -> normalize -> A hi/lo fp16 [px][72] ----
        for (int i = tid; i < 512; i += 256) {
            const int px = i & 63, c0 = (i >> 6) * 8;
            uint32_t hiw[4], low[4];
            #pragma unroll
            for (int j = 0; j < 4; j++) {
                const float v0 = (raw[(c0 + 2 * j)     * 64 + px] - mu) * rs;
                const float v1 = (raw[(c0 + 2 * j + 1) * 64 + px] - mu) * rs;
                split2h(v0, v1, hiw[j], low[j]);
            }
            *(uint4*)(smc + OFF_AHI + px * 144 + c0 * 2) = make_uint4(hiw[0], hiw[1], hiw[2], hiw[3]);
            *(uint4*)(smc + OFF_ALO + px * 144 + c0 * 2) = make_uint4(low[0], low[1], low[2], low[3]);
        }
        __syncthreads();   // A ready; raw[tl] consumed

        // ---- issue cp.async for tile tl+1 (lands under GEMM/epilogue) ----
        if (tl + 1 < TPB) {
            const uint32_t bufn = ((tl + 1) & 1) ? OFF_Z1 : OFF_Z0;
            const int pn = p_base + (tl + 1) * 64;
            for (int i = tid; i < 1024; i += 256) {
                const int c = i >> 4, f = (i & 15) * 4;
                cpasync16(sb + bufn + (c * 64 + f) * 4, zb + (size_t)c * HW + pn + f);
            }
        }
        CP_COMMIT();

        // ---- GEMM1: [16px x 64h] per warp, K=64, 2 split passes ----
        float acc[8][4];
        #pragma unroll
        for (int nt = 0; nt < 8; nt++)
            #pragma unroll
            for (int i = 0; i < 4; i++) acc[nt][i] = 0.f;
        #pragma unroll
        for (int ks = 0; ks < 4; ks++) {
            uint32_t aH[4], aL[4];
            const uint32_t ad = sb + OFF_AHI + (pg * 16 + lrow) * 144 + (ks * 16 + lk * 8) * 2;
            ldsm_x4(aH, ad);
            ldsm_x4(aL, ad + (OFF_ALO - OFF_AHI));
            #pragma unroll
            for (int nt = 0; nt < 8; nt++) {
                const uint32_t bd = sb + OFF_W1 + (hh * 64 + nt * 8 + brow) * 144
                                  + (ks * 16 + bk * 8) * 2;
                uint32_t b0, b1r;
                ldsm_x2(b0, b1r, bd);
                mma_f16(acc[nt], aH, b0, b1r);
                mma_f16(acc[nt], aL, b0, b1r);
            }
        }
        // ---- SiLU(+b1) -> S fp16 [px][136] ----
        #pragma unroll
        for (int nt = 0; nt < 8; nt++) {
            const int h0 = hh * 64 + nt * 8 + 2 * tig;
            const float bi0 = b1s[h0], bi1 = b1s[h0 + 1];
            const float v0 = silu_f(acc[nt][0] + bi0), v1 = silu_f(acc[nt][1] + bi1);
            const float v2 = silu_f(acc[nt][2] + bi0), v3 = silu_f(acc[nt][3] + bi1);
            const uint32_t r0 = (pg * 16 + g) * 272 + h0 * 2;
            const uint32_t r1 = (pg * 16 + g + 8) * 272 + h0 * 2;
            *(uint32_t*)(smc + OFF_S + r0) = packh(__float2half_rn(v0), __float2half_rn(v1));
            *(uint32_t*)(smc + OFF_S + r1) = packh(__float2half_rn(v2), __float2half_rn(v3));
        }
        __syncthreads();   // S complete; A consumed -> Y may reuse A region

        // ---- GEMM2: [16px x 32o] per warp, K=128, 1 pass ----
        float acc2[4][4];
        #pragma unroll
        for (int nt = 0; nt < 4; nt++)
            #pragma unroll
            for (int i = 0; i < 4; i++) acc2[nt][i] = 0.f;
        #pragma unroll
        for (int ks = 0; ks < 8; ks++) {
            uint32_t aH[4];
            ldsm_x4(aH, sb + OFF_S + (pg * 16 + lrow) * 272 + (ks * 16 + lk * 8) * 2);
            #pragma unroll
            for (int nt = 0; nt < 4; nt++) {
                const uint32_t bd = sb + OFF_W2 + (hh * 32 + nt * 8 + brow) * 272
                                  + (ks * 16 + bk * 8) * 2;
                uint32_t b0, b1r;
                ldsm_x2(b0, b1r, bd);
                mma_f16(acc2[nt], aH, b0, b1r);
            }
        }
        // ---- stash y+b2 into Y [o][68] ----
        const int pxl = pg * 16 + g;
        #pragma unroll
        for (int nt = 0; nt < 4; nt++) {
            const int o0 = hh * 32 + nt * 8 + 2 * tig;
            Y[o0 * 68 + pxl]           = acc2[nt][0] + b2s[o0];
            Y[(o0 + 1) * 68 + pxl]     = acc2[nt][1] + b2s[o0 + 1];
            Y[o0 * 68 + pxl + 8]       = acc2[nt][2] + b2s[o0];
            Y[(o0 + 1) * 68 + pxl + 8] = acc2[nt][3] + b2s[o0 + 1];
        }
        __syncthreads();

        // ---- write-out: out[2o] = Y + z0[2o], vectorized ----
        for (int i = tid; i < 1024; i += 256) {       // 64o x 16 float4
            const int o = i >> 4, f = (i & 15) * 4;
            const float4 yv = *(const float4*)(Y + o * 68 + f);
            const float4 rv = *(const float4*)(zb + (size_t)(2 * o) * HW + p0 + f);
            float4 ov;
            ov.x = yv.x + rv.x; ov.y = yv.y + rv.y;
            ov.z = yv.z + rv.z; ov.w = yv.w + rv.w;
            *(float4*)(ob + (size_t)(2 * o) * HW + p0 + f) = ov;
        }
    }
}

// ---------------------------------------------------------------------------
extern "C" void kernel_launch(void* const* d_in, const int* in_sizes, int n_in,
                              void* d_out, int out_size) {
    const float* z0 = (const float*)d_in[0];
    const float* w1 = (const float*)d_in[1];
    const float* b1 = (const float*)d_in[2];
    const float* w2 = (const float*)d_in[3];
    const float* b2 = (const float*)d_in[4];
    float* out = (float*)d_out;

    static bool attr_set = false;
    if (!attr_set) {
        cudaFuncSetAttribute(cp_main_kernel,
                             cudaFuncAttributeMaxDynamicSharedMemorySize,
                             SMEM_MAIN);
        attr_set = true;
    }

    cp_stats_kernel<<<dim3(RED_BLOCKS, NSAMP), RED_THREADS>>>(z0);
    cp_finalize_kernel<<<1, 256>>>(w1, w2);
    cp_main_kernel<<<TOTAL_GRID, 256, SMEM_MAIN>>>(z0, b1, b2, out);
}

// round 12
// speedup vs baseline: 1.1695x; 1.1695x over previous
#include <cuda_runtime.h>
#include <cuda_fp16.h>
#include <cstdint>

// ---------------------------------------------------------------------------
// ChannelProjection via mma.sync (HMMA fp16, base-target ISA).
// R11: 128-px tiles (2x per-phase MLP, half the barriers), 108KB smem,
// 2 CTAs/SM. GEMM1 2-pass fp16-split, GEMM2 1-pass. Uniform grid.
// ---------------------------------------------------------------------------

#define C_TOT   128
#define CC      64
#define HW      36864
#define NSAMP   16
#define CHW     (C_TOT * HW)
#define NPIX    (NSAMP * HW)
#define RED_BLOCKS  64
#define RED_THREADS 256

#define TPB       4                       // 128-px tiles per block
#define BLOCKS_PER_SAMPLE 72              // 72 * 4 * 128 = 36864 px
#define MAIN_GRID (NSAMP * BLOCKS_PER_SAMPLE)   // 1152

// smem offsets; strides: A/W1 rows 144B (72 fp16), S/W2 rows 272B (136 fp16)
#define OFF_W1    0          // [128h][72k]    18432
#define OFF_W2    18432      // [64o][136h]    17408
#define OFF_AHI   35840      // [128px][72k]   18432  (Y fp32 [64o][132] aliases)
#define OFF_ALO   54272      //                18432
#define OFF_S     72704      // [128px][136h]  34816  (fp32 stg [64c][128] aliases)
#define OFF_B1    107520     // 128 f32
#define OFF_B2    108032     // 64 f32
#define SMEM_MAIN 108288

__device__ float g_psum[NSAMP * RED_BLOCKS];
__device__ float g_psq [NSAMP * RED_BLOCKS];
__device__ float g_mu  [NSAMP];
__device__ float g_rs  [NSAMP];
__device__ uint4 g_w1h[1152];   // 128*72 fp16
__device__ uint4 g_w2h[1088];   // 64*136 fp16

// ---------------- helpers ---------------------------------------------------
__device__ __forceinline__ uint32_t smem_u32(const void* p) {
    uint32_t a;
    asm("{ .reg .u64 t; cvta.to.shared.u64 t, %1; cvt.u32.u64 %0, t; }"
        : "=r"(a) : "l"(p));
    return a;
}
__device__ __forceinline__ void ldsm_x4(uint32_t (&r)[4], uint32_t addr) {
    asm volatile("ldmatrix.sync.aligned.m8n8.x4.shared.b16 {%0,%1,%2,%3}, [%4];"
                 : "=r"(r[0]), "=r"(r[1]), "=r"(r[2]), "=r"(r[3]) : "r"(addr));
}
__device__ __forceinline__ void ldsm_x2(uint32_t& r0, uint32_t& r1, uint32_t addr) {
    asm volatile("ldmatrix.sync.aligned.m8n8.x2.shared.b16 {%0,%1}, [%2];"
                 : "=r"(r0), "=r"(r1) : "r"(addr));
}
__device__ __forceinline__ void mma_f16(float (&c)[4], const uint32_t (&a)[4],
                                        uint32_t b0, uint32_t b1) {
    asm volatile(
        "mma.sync.aligned.m16n8k16.row.col.f32.f16.f16.f32 "
        "{%0,%1,%2,%3}, {%4,%5,%6,%7}, {%8,%9}, {%0,%1,%2,%3};"
        : "+f"(c[0]), "+f"(c[1]), "+f"(c[2]), "+f"(c[3])
        : "r"(a[0]), "r"(a[1]), "r"(a[2]), "r"(a[3]), "r"(b0), "r"(b1));
}
__device__ __forceinline__ uint32_t packh(__half a, __half b) {
    __half2 h; h.x = a; h.y = b;
    return *(uint32_t*)&h;
}
__device__ __forceinline__ void split2h(float v0, float v1, uint32_t& hi, uint32_t& lo) {
    const __half h0 = __float2half_rn(v0);
    const __half h1 = __float2half_rn(v1);
    const __half l0 = __float2half_rn(v0 - __half2float(h0));
    const __half l1 = __float2half_rn(v1 - __half2float(h1));
    hi = packh(h0, h1);
    lo = packh(l0, l1);
}
__device__ __forceinline__ float silu_f(float h) {
    return __fdividef(h, 1.f + __expf(-h));
}

// ---------------- stage 1: per-sample partial sums --------------------------
__global__ void cp_stats_kernel(const float* __restrict__ z0) {
    const int b = blockIdx.y;
    const float4* z4 = (const float4*)(z0 + (size_t)b * CHW);
    const int n4 = CHW / 4;
    float s = 0.f, q = 0.f;
    for (int i = blockIdx.x * RED_THREADS + threadIdx.x; i < n4;
         i += RED_BLOCKS * RED_THREADS) {
        float4 v = z4[i];
        s += (v.x + v.y) + (v.z + v.w);
        q += (v.x * v.x + v.y * v.y) + (v.z * v.z + v.w * v.w);
    }
    #pragma unroll
    for (int off = 16; off; off >>= 1) {
        s += __shfl_down_sync(0xffffffffu, s, off);
        q += __shfl_down_sync(0xffffffffu, q, off);
    }
    __shared__ float ss[RED_THREADS / 32], sq[RED_THREADS / 32];
    const int w = threadIdx.x >> 5;
    if ((threadIdx.x & 31) == 0) { ss[w] = s; sq[w] = q; }
    __syncthreads();
    if (threadIdx.x == 0) {
        float S = 0.f, Q = 0.f;
        #pragma unroll
        for (int i = 0; i < RED_THREADS / 32; i++) { S += ss[i]; Q += sq[i]; }
        g_psum[b * RED_BLOCKS + blockIdx.x] = S;
        g_psq [b * RED_BLOCKS + blockIdx.x] = Q;
    }
}

// ---------------- stage 2: finalize + fp16 weights --------------------------
__global__ void cp_finalize_kernel(const float* __restrict__ w1,
                                   const float* __restrict__ w2) {
    const int t = threadIdx.x;   // 256
    if (t < NSAMP) {
        float S = 0.f, Q = 0.f;
        for (int i = 0; i < RED_BLOCKS; i++) {
            S += g_psum[t * RED_BLOCKS + i];
            Q += g_psq [t * RED_BLOCKS + i];
        }
        const float inv_n = 1.f / (float)CHW;
        const float mu  = S * inv_n;
        const float var = Q * inv_n - mu * mu;
        g_mu[t] = mu;
        g_rs[t] = rsqrtf(var + 1e-5f);
    }
    __half* w1h = (__half*)g_w1h;
    __half* w2h = (__half*)g_w2h;
    for (int i = t; i < 128 * 64; i += 256) {      // w1[h][k] -> [h][72]
        const int h = i >> 6, k = i & 63;
        w1h[h * 72 + k] = __float2half_rn(w1[h * 64 + k]);
    }
    for (int i = t; i < 64 * 128; i += 256) {      // w2[o][h] -> [o][136]
        const int o = i >> 7, h = i & 127;
        w2h[o * 136 + h] = __float2half_rn(w2[o * 128 + h]);
    }
}

// ---------------- stage 3: HMMA main kernel (2 CTAs/SM) ---------------------
__global__ void __launch_bounds__(256, 2)
cp_main_kernel(const float* __restrict__ z0,
               const float* __restrict__ b1,
               const float* __restrict__ b2,
               float* __restrict__ out) {
    extern __shared__ char smc[];
    const uint32_t sb = smem_u32(smc);
    const int tid = threadIdx.x;
    const int w = tid >> 5, lane = tid & 31;
    const int g = lane >> 2, tig = lane & 3;
    const int lrow = lane & 15, lk = lane >> 4;          // ldsm.x4 mapping
    const int brow = lane & 7,  bk = (lane >> 3) & 1;    // ldsm.x2 mapping

    // ---- stage weights + biases ----
    for (int i = tid; i < 1152; i += 256) ((uint4*)(smc + OFF_W1))[i] = g_w1h[i];
    for (int i = tid; i < 1088; i += 256) ((uint4*)(smc + OFF_W2))[i] = g_w2h[i];
    float* b1s = (float*)(smc + OFF_B1);
    float* b2s = (float*)(smc + OFF_B2);
    if (tid < 128) b1s[tid] = b1[tid];
    if (tid < 64)  b2s[tid] = b2[tid];

    const int b = blockIdx.x / BLOCKS_PER_SAMPLE;
    const float* zb = z0 + (size_t)b * CHW;
    float*       ob = out + (size_t)b * CHW;
    const int p_base = (blockIdx.x % BLOCKS_PER_SAMPLE) * (TPB * 128);
    const float mu = g_mu[b];
    const float rs = g_rs[b];
    float* stg = (float*)(smc + OFF_S);      // fp32 [c=64][px=128] aliases S
    float* Y   = (float*)(smc + OFF_AHI);    // fp32 [o=64][stride 132] aliases A

    for (int tl = 0; tl < TPB; tl++) {
        const int p0 = p_base + tl * 128;
        __syncthreads();   // prev write-out done (Y/A free); S free

        // ---- staging: raw z1 -> stg (8 independent LDG.128 / thread) ----
        #pragma unroll
        for (int k = 0; k < 8; k++) {
            const int i = tid + k * 256;          // 64ch x 32 float4
            const int c = i >> 5, f = (i & 31) * 4;
            *(float4*)(stg + c * 128 + f) = *(const float4*)(zb + (size_t)c * HW + p0 + f);
        }
        __syncthreads();

        // ---- convert: normalize + split -> A hi/lo fp16 [px][72] ----
        #pragma unroll
        for (int k = 0; k < 4; k++) {
            const int i = tid + k * 256;          // 128px x 8 c-groups
            const int px = i & 127, c0 = (i >> 7) * 8;
            uint32_t hiw[4], low[4];
            #pragma unroll
            for (int j = 0; j < 4; j++) {
                const float v0 = (stg[(c0 + 2 * j)     * 128 + px] - mu) * rs;
                const float v1 = (stg[(c0 + 2 * j + 1) * 128 + px] - mu) * rs;
                split2h(v0, v1, hiw[j], low[j]);
            }
            *(uint4*)(smc + OFF_AHI + px * 144 + c0 * 2) = make_uint4(hiw[0], hiw[1], hiw[2], hiw[3]);
            *(uint4*)(smc + OFF_ALO + px * 144 + c0 * 2) = make_uint4(low[0], low[1], low[2], low[3]);
        }
        __syncthreads();   // A ready; stg consumed (S region free for SiLU)

        // ---- z2 stream: out[2c+1] = norm(z0[64+c]) + z0[2c+1] (16 LDG) ----
        #pragma unroll
        for (int k = 0; k < 8; k++) {
            const int i = tid + k * 256;          // 64ch x 32 float4
            const int c = i >> 5, f = (i & 31) * 4;
            float4 zv = *(const float4*)(zb + (size_t)(CC + c) * HW + p0 + f);
            float4 rv = *(const float4*)(zb + (size_t)(2 * c + 1) * HW + p0 + f);
            float4 ov;
            ov.x = (zv.x - mu) * rs + rv.x; ov.y = (zv.y - mu) * rs + rv.y;
            ov.z = (zv.z - mu) * rs + rv.z; ov.w = (zv.w - mu) * rs + rv.w;
            *(float4*)(ob + (size_t)(2 * c + 1) * HW + p0 + f) = ov;
        }

        // ---- GEMM1: [16px x 128h] per warp, K=64, 2 split passes ----
        float acc[16][4];
        #pragma unroll
        for (int nt = 0; nt < 16; nt++)
            #pragma unroll
            for (int i = 0; i < 4; i++) acc[nt][i] = 0.f;
        #pragma unroll
        for (int ks = 0; ks < 4; ks++) {
            uint32_t aH[4], aL[4];
            const uint32_t ad = sb + OFF_AHI + (w * 16 + lrow) * 144 + (ks * 16 + lk * 8) * 2;
            ldsm_x4(aH, ad);
            ldsm_x4(aL, ad + (OFF_ALO - OFF_AHI));
            #pragma unroll
            for (int nt = 0; nt < 16; nt++) {
                const uint32_t bd = sb + OFF_W1 + (nt * 8 + brow) * 144
                                  + (ks * 16 + bk * 8) * 2;
                uint32_t b0, b1r;
                ldsm_x2(b0, b1r, bd);
                mma_f16(acc[nt], aH, b0, b1r);
                mma_f16(acc[nt], aL, b0, b1r);
            }
        }
        // ---- SiLU(+b1) -> S fp16 [px][136] ----
        #pragma unroll
        for (int nt = 0; nt < 16; nt++) {
            const int h0 = nt * 8 + 2 * tig;
            const float bi0 = b1s[h0], bi1 = b1s[h0 + 1];
            const float v0 = silu_f(acc[nt][0] + bi0), v1 = silu_f(acc[nt][1] + bi1);
            const float v2 = silu_f(acc[nt][2] + bi0), v3 = silu_f(acc[nt][3] + bi1);
            const uint32_t r0 = (w * 16 + g) * 272 + h0 * 2;
            const uint32_t r1 = (w * 16 + g + 8) * 272 + h0 * 2;
            *(uint32_t*)(smc + OFF_S + r0) = packh(__float2half_rn(v0), __float2half_rn(v1));
            *(uint32_t*)(smc + OFF_S + r1) = packh(__float2half_rn(v2), __float2half_rn(v3));
        }
        __syncthreads();   // S complete (each warp wrote its own 16 px rows)

        // ---- GEMM2: [16px x 64o] per warp, K=128, 1 pass ----
        float acc2[8][4];
        #pragma unroll
        for (int nt = 0; nt < 8; nt++)
            #pragma unroll
            for (int i = 0; i < 4; i++) acc2[nt][i] = 0.f;
        #pragma unroll
        for (int ks = 0; ks < 8; ks++) {
            uint32_t aH[4];
            ldsm_x4(aH, sb + OFF_S + (w * 16 + lrow) * 272 + (ks * 16 + lk * 8) * 2);
            #pragma unroll
            for (int nt = 0; nt < 8; nt++) {
                const uint32_t bd = sb + OFF_W2 + (nt * 8 + brow) * 272
                                  + (ks * 16 + bk * 8) * 2;
                uint32_t b0, b1r;
                ldsm_x2(b0, b1r, bd);
                mma_f16(acc2[nt], aH, b0, b1r);
            }
        }
        // ---- stash y+b2 into Y [o][132] (conflict-free) ----
        const int pxl = w * 16 + g;
        #pragma unroll
        for (int nt = 0; nt < 8; nt++) {
            const int o0 = nt * 8 + 2 * tig;
            Y[o0 * 132 + pxl]           = acc2[nt][0] + b2s[o0];
            Y[(o0 + 1) * 132 + pxl]     = acc2[nt][1] + b2s[o0 + 1];
            Y[o0 * 132 + pxl + 8]       = acc2[nt][2] + b2s[o0];
            Y[(o0 + 1) * 132 + pxl + 8] = acc2[nt][3] + b2s[o0 + 1];
        }
        __syncthreads();

        // ---- write-out: out[2o] = Y + z0[2o] (8 LDG + 8 STG / thread) ----
        #pragma unroll
        for (int k = 0; k < 8; k++) {
            const int i = tid + k * 256;          // 64o x 32 float4
            const int o = i >> 5, f = (i & 31) * 4;
            const float4 yv = *(const float4*)(Y + o * 132 + f);
            const float4 rv = *(const float4*)(zb + (size_t)(2 * o) * HW + p0 + f);
            float4 ov;
            ov.x = yv.x + rv.x; ov.y = yv.y + rv.y;
            ov.z = yv.z + rv.z; ov.w = yv.w + rv.w;
            *(float4*)(ob + (size_t)(2 * o) * HW + p0 + f) = ov;
        }
    }
}

// ---------------------------------------------------------------------------
extern "C" void kernel_launch(void* const* d_in, const int* in_sizes, int n_in,
                              void* d_out, int out_size) {
    const float* z0 = (const float*)d_in[0];
    const float* w1 = (const float*)d_in[1];
    const float* b1 = (const float*)d_in[2];
    const float* w2 = (const float*)d_in[3];
    const float* b2 = (const float*)d_in[4];
    float* out = (float*)d_out;

    static bool attr_set = false;
    if (!attr_set) {
        cudaFuncSetAttribute(cp_main_kernel,
                             cudaFuncAttributeMaxDynamicSharedMemorySize,
                             SMEM_MAIN);
        attr_set = true;
    }

    cp_stats_kernel<<<dim3(RED_BLOCKS, NSAMP), RED_THREADS>>>(z0);
    cp_finalize_kernel<<<1, 256>>>(w1, w2);
    cp_main_kernel<<<MAIN_GRID, 256, SMEM_MAIN>>>(z0, b1, b2, out);
}